// round 1
// baseline (speedup 1.0000x reference)
#include <cuda_runtime.h>
#include <math.h>

#define BB 8
#define LL 1000
#define DMODEL 512
#define HH 8
#define DK 64
#define PDIM 16
#define DFF 2048
#define NLAYERS 4
#define NPRED 50
#define ROWS (BB*LL)            /* 8000 */
#define LEPS 1e-5f
#define QKSCALE 0.125f          /* 1/sqrt(64) */

/* ------------------------- scratch (device globals; no allocs) ------------------------- */
__device__ float g_h   [ROWS*DMODEL];
__device__ float g_q   [ROWS*DMODEL];
__device__ float g_k   [ROWS*DMODEL];
__device__ float g_v   [ROWS*DMODEL];
__device__ float g_ctx [ROWS*DMODEL];
__device__ float g_y   [ROWS*DMODEL];
__device__ float g_qp  [ROWS*HH*PDIM];
__device__ float g_kp  [ROWS*HH*PDIM];
__device__ float g_ffn [ROWS*DFF];
__device__ float g_scores[(size_t)BB*HH*LL*LL];   /* 256 MB */

/* ------------------------- reductions ------------------------- */
__device__ __forceinline__ float block_reduce_sum(float v, float* sbuf) {
    int t = threadIdx.x;
    #pragma unroll
    for (int o = 16; o > 0; o >>= 1) v += __shfl_xor_sync(0xffffffffu, v, o);
    if ((t & 31) == 0) sbuf[t >> 5] = v;
    __syncthreads();
    if (t < 32) {
        float w = (t < (int)(blockDim.x >> 5)) ? sbuf[t] : 0.f;
        #pragma unroll
        for (int o = 16; o > 0; o >>= 1) w += __shfl_xor_sync(0xffffffffu, w, o);
        if (t == 0) sbuf[0] = w;
    }
    __syncthreads();
    float r = sbuf[0];
    __syncthreads();
    return r;
}

__device__ __forceinline__ float block_reduce_max(float v, float* sbuf) {
    int t = threadIdx.x;
    #pragma unroll
    for (int o = 16; o > 0; o >>= 1) v = fmaxf(v, __shfl_xor_sync(0xffffffffu, v, o));
    if ((t & 31) == 0) sbuf[t >> 5] = v;
    __syncthreads();
    if (t < 32) {
        float w = (t < (int)(blockDim.x >> 5)) ? sbuf[t] : -3.4e38f;
        #pragma unroll
        for (int o = 16; o > 0; o >>= 1) w = fmaxf(w, __shfl_xor_sync(0xffffffffu, w, o));
        if (t == 0) sbuf[0] = w;
    }
    __syncthreads();
    float r = sbuf[0];
    __syncthreads();
    return r;
}

/* ------------------------- embedding: h = x @ emb_w + emb_b + pe ------------------------- */
__global__ void embed_kernel(const float* __restrict__ x, const float* __restrict__ ew,
                             const float* __restrict__ eb, const float* __restrict__ pe,
                             float* __restrict__ h) {
    int r = blockIdx.x;                 /* 0..7999 */
    int t = threadIdx.x;                /* 256 */
    __shared__ float xs[7];
    if (t < 7) xs[t] = x[(size_t)r*7 + t];
    __syncthreads();
    int l = r % LL;
    for (int d = t; d < DMODEL; d += 256) {
        float s = eb[d] + pe[(size_t)l*DMODEL + d];
        #pragma unroll
        for (int f = 0; f < 7; f++) s += xs[f]*ew[(size_t)f*DMODEL + d];
        h[(size_t)r*DMODEL + d] = s;
    }
}

/* ------------------------- generic SGEMM: C[M,N] = A[M,K] @ B[K,N] + bias (opt relu) -----
   BM=BN=128, BK=8, 256 threads, 8x8 per thread. N % 128 == 0, K % 8 == 0 required. */
template<int RELU>
__global__ __launch_bounds__(256) void sgemm_bias(const float* __restrict__ A,
                                                  const float* __restrict__ Bm,
                                                  const float* __restrict__ bias,
                                                  float* __restrict__ C,
                                                  int M, int N, int K) {
    __shared__ float As[8][128];
    __shared__ float Bs[8][128];
    int tid = threadIdx.x;
    int row0 = blockIdx.y * 128;
    int col0 = blockIdx.x * 128;
    int aRow = tid >> 1;
    int aCol = (tid & 1) * 4;
    int bRow = tid >> 5;
    int bCol = (tid & 31) * 4;
    int tx = tid & 15, ty = tid >> 4;

    float acc[8][8];
    #pragma unroll
    for (int i = 0; i < 8; i++)
        #pragma unroll
        for (int j = 0; j < 8; j++) acc[i][j] = 0.f;

    for (int kt = 0; kt < K; kt += 8) {
        float4 av = make_float4(0.f, 0.f, 0.f, 0.f);
        int gr = row0 + aRow;
        if (gr < M) av = *(const float4*)(A + (size_t)gr*K + kt + aCol);
        As[aCol+0][aRow] = av.x;
        As[aCol+1][aRow] = av.y;
        As[aCol+2][aRow] = av.z;
        As[aCol+3][aRow] = av.w;
        *(float4*)&Bs[bRow][bCol] = *(const float4*)(Bm + (size_t)(kt + bRow)*N + col0 + bCol);
        __syncthreads();
        #pragma unroll
        for (int kk = 0; kk < 8; kk++) {
            float ar[8], br[8];
            *(float4*)(ar)   = *(float4*)&As[kk][ty*8];
            *(float4*)(ar+4) = *(float4*)&As[kk][ty*8+4];
            *(float4*)(br)   = *(float4*)&Bs[kk][tx*8];
            *(float4*)(br+4) = *(float4*)&Bs[kk][tx*8+4];
            #pragma unroll
            for (int i = 0; i < 8; i++)
                #pragma unroll
                for (int j = 0; j < 8; j++)
                    acc[i][j] += ar[i]*br[j];
        }
        __syncthreads();
    }

    #pragma unroll
    for (int i = 0; i < 8; i++) {
        int gr = row0 + ty*8 + i;
        if (gr >= M) continue;
        #pragma unroll
        for (int j = 0; j < 8; j++) {
            int gc = col0 + tx*8 + j;
            float c = acc[i][j] + bias[gc];
            if (RELU) c = fmaxf(c, 0.f);
            C[(size_t)gr*N + gc] = c;
        }
    }
}

/* ------------------------- learned-mask projection: qp = q(head) @ w + b ----------------- */
__global__ void lmproj_kernel(const float* __restrict__ q, const float* __restrict__ w,
                              const float* __restrict__ bias, float* __restrict__ out) {
    __shared__ float row[DMODEL];
    int r = blockIdx.x;        /* 8000 */
    int t = threadIdx.x;       /* 128 */
    row[t]       = q[(size_t)r*DMODEL + t];
    row[t+128]   = q[(size_t)r*DMODEL + t + 128];
    row[t+256]   = q[(size_t)r*DMODEL + t + 256];
    row[t+384]   = q[(size_t)r*DMODEL + t + 384];
    __syncthreads();
    int h = t >> 4, p = t & 15;
    float s = bias[p];
    #pragma unroll
    for (int d = 0; d < DK; d++) s += row[h*DK + d]*w[d*PDIM + p];
    out[(size_t)r*(HH*PDIM) + t] = s;
}

/* ------------------------- scores = scale*q.kT + tanh(qp.kpT), per (b,h) ----------------
   64x64 tile, depth 80 (64 qk + 16 mask) in smem. */
__global__ __launch_bounds__(256) void scores_kernel(const float* __restrict__ q,
                                                     const float* __restrict__ k,
                                                     const float* __restrict__ qp,
                                                     const float* __restrict__ kp,
                                                     float* __restrict__ scores) {
    __shared__ float qs[64][81];
    __shared__ float ks[64][81];
    int bh = blockIdx.z;
    int b = bh >> 3, h = bh & 7;
    int l0 = blockIdx.y * 64;
    int s0 = blockIdx.x * 64;
    int tid = threadIdx.x;

    for (int idx = tid; idx < 64*64; idx += 256) {
        int li = idx >> 6, d = idx & 63;
        int l = l0 + li;
        qs[li][d] = (l < LL) ? q[(size_t)(b*LL + l)*DMODEL + h*DK + d] : 0.f;
        int s = s0 + li;
        ks[li][d] = (s < LL) ? k[(size_t)(b*LL + s)*DMODEL + h*DK + d] : 0.f;
    }
    for (int idx = tid; idx < 64*16; idx += 256) {
        int li = idx >> 4, p = idx & 15;
        int l = l0 + li;
        qs[li][64+p] = (l < LL) ? qp[(size_t)(b*LL + l)*(HH*PDIM) + h*PDIM + p] : 0.f;
        int s = s0 + li;
        ks[li][64+p] = (s < LL) ? kp[(size_t)(b*LL + s)*(HH*PDIM) + h*PDIM + p] : 0.f;
    }
    __syncthreads();

    int tx = tid & 15, ty = tid >> 4;
    int li0 = ty*4, si0 = tx*4;
    float acc[4][4], accm[4][4];
    #pragma unroll
    for (int i = 0; i < 4; i++)
        #pragma unroll
        for (int j = 0; j < 4; j++) { acc[i][j] = 0.f; accm[i][j] = 0.f; }

    #pragma unroll 8
    for (int d = 0; d < 64; d++) {
        float a[4], bv[4];
        #pragma unroll
        for (int i = 0; i < 4; i++) a[i]  = qs[li0+i][d];
        #pragma unroll
        for (int j = 0; j < 4; j++) bv[j] = ks[si0+j][d];
        #pragma unroll
        for (int i = 0; i < 4; i++)
            #pragma unroll
            for (int j = 0; j < 4; j++)
                acc[i][j] += a[i]*bv[j];
    }
    #pragma unroll
    for (int d = 64; d < 80; d++) {
        float a[4], bv[4];
        #pragma unroll
        for (int i = 0; i < 4; i++) a[i]  = qs[li0+i][d];
        #pragma unroll
        for (int j = 0; j < 4; j++) bv[j] = ks[si0+j][d];
        #pragma unroll
        for (int i = 0; i < 4; i++)
            #pragma unroll
            for (int j = 0; j < 4; j++)
                accm[i][j] += a[i]*bv[j];
    }

    size_t base = (size_t)bh * LL * LL;
    #pragma unroll
    for (int i = 0; i < 4; i++) {
        int l = l0 + li0 + i;
        if (l >= LL) continue;
        #pragma unroll
        for (int j = 0; j < 4; j++) {
            int s = s0 + si0 + j;
            if (s >= LL) continue;
            scores[base + (size_t)l*LL + s] = acc[i][j]*QKSCALE + tanhf(accm[i][j]);
        }
    }
}

/* ------------------------- row softmax over last dim (1000) ------------------------- */
__global__ void softmax_kernel(float* __restrict__ scores) {
    __shared__ float sbuf[32];
    size_t r = blockIdx.x;              /* 64000 rows */
    float* row = scores + r*LL;
    int t = threadIdx.x;                /* 256 */
    float vals[4];
    float m = -3.4e38f;
    #pragma unroll
    for (int kk = 0; kk < 4; kk++) {
        int i = t + kk*256;
        vals[kk] = (i < LL) ? row[i] : -3.4e38f;
        m = fmaxf(m, vals[kk]);
    }
    m = block_reduce_max(m, sbuf);
    float s = 0.f;
    #pragma unroll
    for (int kk = 0; kk < 4; kk++) {
        int i = t + kk*256;
        if (i < LL) { vals[kk] = expf(vals[kk] - m); s += vals[kk]; }
    }
    s = block_reduce_sum(s, sbuf);
    float inv = 1.f/s;
    #pragma unroll
    for (int kk = 0; kk < 4; kk++) {
        int i = t + kk*256;
        if (i < LL) row[i] = vals[kk]*inv;
    }
}

/* ------------------------- ctx = attn @ v, per (b,h): M=1000,N=64,K=1000 ----------------- */
__global__ __launch_bounds__(256) void ctx_kernel(const float* __restrict__ attn,
                                                  const float* __restrict__ v,
                                                  float* __restrict__ ctx) {
    __shared__ float at[64][33];   /* [l][s] tile, padded */
    __shared__ float vs[32][64];   /* [s][d] tile */
    int bh = blockIdx.z;
    int b = bh >> 3, h = bh & 7;
    int l0 = blockIdx.x * 64;
    int tid = threadIdx.x;
    int tx = tid & 15, ty = tid >> 4;

    float acc[4][4];
    #pragma unroll
    for (int i = 0; i < 4; i++)
        #pragma unroll
        for (int j = 0; j < 4; j++) acc[i][j] = 0.f;

    size_t abase = (size_t)bh * LL * LL;
    for (int s0 = 0; s0 < LL; s0 += 32) {
        for (int idx = tid; idx < 64*32; idx += 256) {
            int li = idx >> 5, si = idx & 31;
            int l = l0 + li, s = s0 + si;
            at[li][si] = (l < LL && s < LL) ? attn[abase + (size_t)l*LL + s] : 0.f;
        }
        for (int idx = tid; idx < 32*64; idx += 256) {
            int si = idx >> 6, d = idx & 63;
            int s = s0 + si;
            vs[si][d] = (s < LL) ? v[(size_t)(b*LL + s)*DMODEL + h*DK + d] : 0.f;
        }
        __syncthreads();
        #pragma unroll 8
        for (int s = 0; s < 32; s++) {
            float a[4], bv[4];
            #pragma unroll
            for (int i = 0; i < 4; i++) a[i] = at[ty*4+i][s];
            *(float4*)bv = *(float4*)&vs[s][tx*4];
            #pragma unroll
            for (int i = 0; i < 4; i++)
                #pragma unroll
                for (int j = 0; j < 4; j++)
                    acc[i][j] += a[i]*bv[j];
        }
        __syncthreads();
    }

    #pragma unroll
    for (int i = 0; i < 4; i++) {
        int l = l0 + ty*4 + i;
        if (l >= LL) continue;
        #pragma unroll
        for (int j = 0; j < 4; j++) {
            int d = tx*4 + j;
            ctx[(size_t)(b*LL + l)*DMODEL + h*DK + d] = acc[i][j];
        }
    }
}

/* ------------------------- h = LN(h + res) ------------------------- */
__global__ void ln_residual_kernel(float* __restrict__ h, const float* __restrict__ res,
                                   const float* __restrict__ g, const float* __restrict__ b) {
    __shared__ float sbuf[32];
    int r = blockIdx.x, t = threadIdx.x;   /* 256 */
    size_t base = (size_t)r*DMODEL;
    float v0 = h[base + t]       + res[base + t];
    float v1 = h[base + t + 256] + res[base + t + 256];
    float mean = block_reduce_sum(v0 + v1, sbuf) * (1.f/DMODEL);
    float d0 = v0 - mean, d1 = v1 - mean;
    float var = block_reduce_sum(d0*d0 + d1*d1, sbuf) * (1.f/DMODEL);
    float inv = rsqrtf(var + LEPS);
    h[base + t]       = d0*inv*g[t]     + b[t];
    h[base + t + 256] = d1*inv*g[t+256] + b[t+256];
}

/* ------------------------- h = LN(LN(h+y)+y)  (the double-norm2 quirk) ------------------- */
__global__ void double_ln_kernel(float* __restrict__ h, const float* __restrict__ y,
                                 const float* __restrict__ g, const float* __restrict__ b) {
    __shared__ float sbuf[32];
    int r = blockIdx.x, t = threadIdx.x;   /* 256 */
    size_t base = (size_t)r*DMODEL;
    float y0 = y[base + t], y1 = y[base + t + 256];
    float t0 = h[base + t] + y0, t1 = h[base + t + 256] + y1;
    float mean = block_reduce_sum(t0 + t1, sbuf) * (1.f/DMODEL);
    float d0 = t0 - mean, d1 = t1 - mean;
    float var = block_reduce_sum(d0*d0 + d1*d1, sbuf) * (1.f/DMODEL);
    float inv = rsqrtf(var + LEPS);
    float h20 = d0*inv*g[t]     + b[t];
    float h21 = d1*inv*g[t+256] + b[t+256];
    /* second LN of (h2 + y) */
    float u0 = h20 + y0, u1 = h21 + y1;
    mean = block_reduce_sum(u0 + u1, sbuf) * (1.f/DMODEL);
    d0 = u0 - mean; d1 = u1 - mean;
    var = block_reduce_sum(d0*d0 + d1*d1, sbuf) * (1.f/DMODEL);
    inv = rsqrtf(var + LEPS);
    h[base + t]       = d0*inv*g[t]     + b[t];
    h[base + t + 256] = d1*inv*g[t+256] + b[t+256];
}

/* ------------------------- final: LN(last token) @ fc_w + fc_b ------------------------- */
__global__ void final_kernel(const float* __restrict__ h, const float* __restrict__ gn,
                             const float* __restrict__ bn, const float* __restrict__ fw,
                             const float* __restrict__ fb, float* __restrict__ out) {
    __shared__ float sbuf[32];
    __shared__ float row[DMODEL];
    int b = blockIdx.x, t = threadIdx.x;   /* 256 */
    const float* hr = h + (size_t)(b*LL + (LL-1))*DMODEL;
    float v0 = hr[t], v1 = hr[t + 256];
    float mean = block_reduce_sum(v0 + v1, sbuf) * (1.f/DMODEL);
    float d0 = v0 - mean, d1 = v1 - mean;
    float var = block_reduce_sum(d0*d0 + d1*d1, sbuf) * (1.f/DMODEL);
    float inv = rsqrtf(var + LEPS);
    row[t]       = d0*inv*gn[t]     + bn[t];
    row[t + 256] = d1*inv*gn[t+256] + bn[t+256];
    __syncthreads();
    for (int p = t; p < NPRED; p += 256) {
        float s = fb[p];
        for (int d = 0; d < DMODEL; d++) s += row[d]*fw[(size_t)d*NPRED + p];
        out[(size_t)b*NPRED + p] = s;
    }
}

/* ------------------------- launch ------------------------- */
extern "C" void kernel_launch(void* const* d_in, const int* in_sizes, int n_in,
                              void* d_out, int out_size) {
    const float* x     = (const float*)d_in[0];
    const float* emb_w = (const float*)d_in[1];
    const float* emb_b = (const float*)d_in[2];
    const float* pe    = (const float*)d_in[3];
    const float* Wq    = (const float*)d_in[4];
    const float* bq    = (const float*)d_in[5];
    const float* Wk    = (const float*)d_in[6];
    const float* bk    = (const float*)d_in[7];
    const float* Wv    = (const float*)d_in[8];
    const float* bv    = (const float*)d_in[9];
    const float* Wo    = (const float*)d_in[10];
    const float* bo    = (const float*)d_in[11];
    const float* W1    = (const float*)d_in[12];
    const float* b1    = (const float*)d_in[13];
    const float* W2    = (const float*)d_in[14];
    const float* b2    = (const float*)d_in[15];
    const float* g1    = (const float*)d_in[16];
    const float* be1   = (const float*)d_in[17];
    const float* g2    = (const float*)d_in[18];
    const float* be2   = (const float*)d_in[19];
    const float* lm_qw = (const float*)d_in[20];
    const float* lm_qb = (const float*)d_in[21];
    const float* lm_kw = (const float*)d_in[22];
    const float* lm_kb = (const float*)d_in[23];
    const float* gn    = (const float*)d_in[24];
    const float* bn    = (const float*)d_in[25];
    const float* fc_w  = (const float*)d_in[26];
    const float* fc_b  = (const float*)d_in[27];
    float* out = (float*)d_out;

    float *h, *q, *k, *v, *ctx, *y, *qp, *kp, *ffn, *scores;
    cudaGetSymbolAddress((void**)&h,      g_h);
    cudaGetSymbolAddress((void**)&q,      g_q);
    cudaGetSymbolAddress((void**)&k,      g_k);
    cudaGetSymbolAddress((void**)&v,      g_v);
    cudaGetSymbolAddress((void**)&ctx,    g_ctx);
    cudaGetSymbolAddress((void**)&y,      g_y);
    cudaGetSymbolAddress((void**)&qp,     g_qp);
    cudaGetSymbolAddress((void**)&kp,     g_kp);
    cudaGetSymbolAddress((void**)&ffn,    g_ffn);
    cudaGetSymbolAddress((void**)&scores, g_scores);

    embed_kernel<<<ROWS, 256>>>(x, emb_w, emb_b, pe, h);

    dim3 g512(DMODEL/128, (ROWS + 127)/128);
    dim3 gff (DFF/128,    (ROWS + 127)/128);
    dim3 gsc (16, 16, BB*HH);
    dim3 gcx (16, 1, BB*HH);

    for (int i = 0; i < NLAYERS; i++) {
        const float* Wq_i = Wq + (size_t)i*DMODEL*DMODEL;
        const float* Wk_i = Wk + (size_t)i*DMODEL*DMODEL;
        const float* Wv_i = Wv + (size_t)i*DMODEL*DMODEL;
        const float* Wo_i = Wo + (size_t)i*DMODEL*DMODEL;
        const float* bq_i = bq + (size_t)i*DMODEL;
        const float* bk_i = bk + (size_t)i*DMODEL;
        const float* bv_i = bv + (size_t)i*DMODEL;
        const float* bo_i = bo + (size_t)i*DMODEL;
        const float* W1_i = W1 + (size_t)i*DMODEL*DFF;
        const float* b1_i = b1 + (size_t)i*DFF;
        const float* W2_i = W2 + (size_t)i*DFF*DMODEL;
        const float* b2_i = b2 + (size_t)i*DMODEL;
        const float* g1_i = g1 + (size_t)i*DMODEL;
        const float* be1_i= be1+ (size_t)i*DMODEL;
        const float* g2_i = g2 + (size_t)i*DMODEL;
        const float* be2_i= be2+ (size_t)i*DMODEL;

        sgemm_bias<0><<<g512, 256>>>(h, Wq_i, bq_i, q, ROWS, DMODEL, DMODEL);
        sgemm_bias<0><<<g512, 256>>>(h, Wk_i, bk_i, k, ROWS, DMODEL, DMODEL);
        sgemm_bias<0><<<g512, 256>>>(h, Wv_i, bv_i, v, ROWS, DMODEL, DMODEL);

        lmproj_kernel<<<ROWS, 128>>>(q, lm_qw, lm_qb, qp);
        lmproj_kernel<<<ROWS, 128>>>(k, lm_kw, lm_kb, kp);

        scores_kernel<<<gsc, 256>>>(q, k, qp, kp, scores);
        softmax_kernel<<<BB*HH*LL, 256>>>(scores);
        ctx_kernel<<<gcx, 256>>>(scores, v, ctx);

        /* o-projection reuses q buffer */
        sgemm_bias<0><<<g512, 256>>>(ctx, Wo_i, bo_i, q, ROWS, DMODEL, DMODEL);
        ln_residual_kernel<<<ROWS, 256>>>(h, q, g1_i, be1_i);

        sgemm_bias<1><<<gff, 256>>>(h, W1_i, b1_i, ffn, ROWS, DFF, DMODEL);
        sgemm_bias<0><<<g512, 256>>>(ffn, W2_i, b2_i, y, ROWS, DMODEL, DFF);
        double_ln_kernel<<<ROWS, 256>>>(h, y, g2_i, be2_i);
    }

    final_kernel<<<BB, 256>>>(h, gn, bn, fc_w, fc_b, out);
    (void)in_sizes; (void)n_in; (void)out_size;
}

// round 2
// speedup vs baseline: 1.6697x; 1.6697x over previous
#include <cuda_runtime.h>
#include <math.h>

#define BB 8
#define LL 1000
#define DMODEL 512
#define HH 8
#define DK 64
#define PDIM 16
#define DFF 2048
#define NLAYERS 4
#define NPRED 50
#define ROWS (BB*LL)            /* 8000 */
#define LEPS 1e-5f
#define QKSCALE 0.125f          /* 1/sqrt(64) */

/* ------------------------- scratch (device globals; no allocs) ------------------------- */
__device__ float g_h   [ROWS*DMODEL];
__device__ float g_q   [ROWS*DMODEL];
__device__ float g_k   [ROWS*DMODEL];
__device__ float g_v   [ROWS*DMODEL];
__device__ float g_ctx [ROWS*DMODEL];
__device__ float g_y   [ROWS*DMODEL];
__device__ float g_qp  [ROWS*HH*PDIM];
__device__ float g_kp  [ROWS*HH*PDIM];
__device__ float g_ffn [ROWS*DFF];
__device__ float g_scores[(size_t)BB*HH*LL*LL];   /* 256 MB */

/* ------------------------- reductions ------------------------- */
__device__ __forceinline__ float block_reduce_sum(float v, float* sbuf) {
    int t = threadIdx.x;
    #pragma unroll
    for (int o = 16; o > 0; o >>= 1) v += __shfl_xor_sync(0xffffffffu, v, o);
    if ((t & 31) == 0) sbuf[t >> 5] = v;
    __syncthreads();
    if (t < 32) {
        float w = (t < (int)(blockDim.x >> 5)) ? sbuf[t] : 0.f;
        #pragma unroll
        for (int o = 16; o > 0; o >>= 1) w += __shfl_xor_sync(0xffffffffu, w, o);
        if (t == 0) sbuf[0] = w;
    }
    __syncthreads();
    float r = sbuf[0];
    __syncthreads();
    return r;
}

__device__ __forceinline__ float block_reduce_max(float v, float* sbuf) {
    int t = threadIdx.x;
    #pragma unroll
    for (int o = 16; o > 0; o >>= 1) v = fmaxf(v, __shfl_xor_sync(0xffffffffu, v, o));
    if ((t & 31) == 0) sbuf[t >> 5] = v;
    __syncthreads();
    if (t < 32) {
        float w = (t < (int)(blockDim.x >> 5)) ? sbuf[t] : -3.4e38f;
        #pragma unroll
        for (int o = 16; o > 0; o >>= 1) w = fmaxf(w, __shfl_xor_sync(0xffffffffu, w, o));
        if (t == 0) sbuf[0] = w;
    }
    __syncthreads();
    float r = sbuf[0];
    __syncthreads();
    return r;
}

/* ------------------------- tf32 helpers ------------------------- */
__device__ __forceinline__ unsigned f2tf(float x) {
    unsigned r;
    asm("cvt.rna.tf32.f32 %0, %1;" : "=r"(r) : "f"(x));
    return r;
}

__device__ __forceinline__ void mma_tf32(float c[4], unsigned a0, unsigned a1,
                                         unsigned a2, unsigned a3,
                                         unsigned b0, unsigned b1) {
    asm volatile(
        "mma.sync.aligned.m16n8k8.row.col.f32.tf32.tf32.f32 "
        "{%0,%1,%2,%3}, {%4,%5,%6,%7}, {%8,%9}, {%0,%1,%2,%3};\n"
        : "+f"(c[0]), "+f"(c[1]), "+f"(c[2]), "+f"(c[3])
        : "r"(a0), "r"(a1), "r"(a2), "r"(a3), "r"(b0), "r"(b1));
}

/* ------------------------- embedding: h = x @ emb_w + emb_b + pe ------------------------- */
__global__ void embed_kernel(const float* __restrict__ x, const float* __restrict__ ew,
                             const float* __restrict__ eb, const float* __restrict__ pe,
                             float* __restrict__ h) {
    int r = blockIdx.x;                 /* 0..7999 */
    int t = threadIdx.x;                /* 256 */
    __shared__ float xs[7];
    if (t < 7) xs[t] = x[(size_t)r*7 + t];
    __syncthreads();
    int l = r % LL;
    for (int d = t; d < DMODEL; d += 256) {
        float s = eb[d] + pe[(size_t)l*DMODEL + d];
        #pragma unroll
        for (int f = 0; f < 7; f++) s += xs[f]*ew[(size_t)f*DMODEL + d];
        h[(size_t)r*DMODEL + d] = s;
    }
}

/* ------------------------- tf32 tensor-core GEMM ---------------------------------------
   C[M,N] = A[M,K] @ B[K,N] + bias, optional ReLU.  BM=BN=128, BK=16, 256 threads.
   8 warps: warp_m = wid&1 (64 rows), warp_n = wid>>1 (32 cols). 16 m16n8k8 mma per k8.
   As[m][k] pitch 20 (frag loads bank-conflict-free: 20g mod 32 distinct over g=0..7).
   Bs[k][n] pitch 136 (8*tg+g distinct). Requirements: N%128==0, K%16==0; M guarded. */
#define APITCH 20
#define BPITCH 136
template<int RELU>
__global__ __launch_bounds__(256, 2) void gemm_tf32(const float* __restrict__ A,
                                                    const float* __restrict__ Bm,
                                                    const float* __restrict__ bias,
                                                    float* __restrict__ C,
                                                    int M, int N, int K) {
    __shared__ unsigned As[2][128*APITCH];
    __shared__ unsigned Bs[2][16*BPITCH];

    int tid  = threadIdx.x;
    int lane = tid & 31;
    int wid  = tid >> 5;
    int g    = lane >> 2;
    int tg   = lane & 3;
    int warp_m = wid & 1;
    int warp_n = wid >> 1;

    int row0 = blockIdx.y * 128;
    int col0 = blockIdx.x * 128;

    /* global load indices */
    int ar  = tid >> 2;           /* 0..63: A tile row within pass     */
    int akq = (tid & 3) * 4;      /* k offset (float4)                 */
    int bk  = tid >> 5;           /* 0..7: B tile k row within pass    */
    int bn  = (tid & 31) * 4;     /* n offset (float4)                 */

    float acc[4][4][4];
    #pragma unroll
    for (int mt = 0; mt < 4; mt++)
        #pragma unroll
        for (int nt = 0; nt < 4; nt++)
            #pragma unroll
            for (int c = 0; c < 4; c++) acc[mt][nt][c] = 0.f;

    int nslab = K >> 4;

    float4 pa[2], pb[2];

    /* prologue: load slab 0 into regs, store to buffer 0 */
    {
        #pragma unroll
        for (int p = 0; p < 2; p++) {
            int r = row0 + ar + p*64;
            pa[p] = (r < M) ? *(const float4*)(A + (size_t)r*K + akq)
                            : make_float4(0.f,0.f,0.f,0.f);
            int kk = bk + p*8;
            pb[p] = *(const float4*)(Bm + (size_t)kk*N + col0 + bn);
        }
        #pragma unroll
        for (int p = 0; p < 2; p++) {
            unsigned* as = &As[0][(ar + p*64)*APITCH + akq];
            as[0] = f2tf(pa[p].x); as[1] = f2tf(pa[p].y);
            as[2] = f2tf(pa[p].z); as[3] = f2tf(pa[p].w);
            unsigned* bs = &Bs[0][(bk + p*8)*BPITCH + bn];
            bs[0] = f2tf(pb[p].x); bs[1] = f2tf(pb[p].y);
            bs[2] = f2tf(pb[p].z); bs[3] = f2tf(pb[p].w);
        }
    }
    __syncthreads();

    for (int s = 0; s < nslab; s++) {
        int cur = s & 1;
        int nxt = cur ^ 1;
        int kt  = (s + 1) << 4;

        if (s + 1 < nslab) {
            #pragma unroll
            for (int p = 0; p < 2; p++) {
                int r = row0 + ar + p*64;
                pa[p] = (r < M) ? *(const float4*)(A + (size_t)r*K + kt + akq)
                                : make_float4(0.f,0.f,0.f,0.f);
                int kk = kt + bk + p*8;
                pb[p] = *(const float4*)(Bm + (size_t)kk*N + col0 + bn);
            }
        }

        /* compute current slab: 2 k8 steps */
        #pragma unroll
        for (int ks = 0; ks < 2; ks++) {
            int kb = ks * 8;
            unsigned af[4][4];
            #pragma unroll
            for (int mt = 0; mt < 4; mt++) {
                int m0 = warp_m*64 + mt*16;
                af[mt][0] = As[cur][(m0 + g    )*APITCH + kb + tg    ];
                af[mt][1] = As[cur][(m0 + g + 8)*APITCH + kb + tg    ];
                af[mt][2] = As[cur][(m0 + g    )*APITCH + kb + tg + 4];
                af[mt][3] = As[cur][(m0 + g + 8)*APITCH + kb + tg + 4];
            }
            unsigned bf[4][2];
            #pragma unroll
            for (int nt = 0; nt < 4; nt++) {
                int n0 = warp_n*32 + nt*8;
                bf[nt][0] = Bs[cur][(kb + tg    )*BPITCH + n0 + g];
                bf[nt][1] = Bs[cur][(kb + tg + 4)*BPITCH + n0 + g];
            }
            #pragma unroll
            for (int mt = 0; mt < 4; mt++)
                #pragma unroll
                for (int nt = 0; nt < 4; nt++)
                    mma_tf32(acc[mt][nt], af[mt][0], af[mt][1], af[mt][2], af[mt][3],
                             bf[nt][0], bf[nt][1]);
        }

        if (s + 1 < nslab) {
            #pragma unroll
            for (int p = 0; p < 2; p++) {
                unsigned* as = &As[nxt][(ar + p*64)*APITCH + akq];
                as[0] = f2tf(pa[p].x); as[1] = f2tf(pa[p].y);
                as[2] = f2tf(pa[p].z); as[3] = f2tf(pa[p].w);
                unsigned* bs = &Bs[nxt][(bk + p*8)*BPITCH + bn];
                bs[0] = f2tf(pb[p].x); bs[1] = f2tf(pb[p].y);
                bs[2] = f2tf(pb[p].z); bs[3] = f2tf(pb[p].w);
            }
        }
        __syncthreads();
    }

    /* epilogue: C layout per mma: c0 at (g, tg*2), c1 (g, tg*2+1), c2 (g+8, tg*2), c3 (g+8, tg*2+1) */
    #pragma unroll
    for (int mt = 0; mt < 4; mt++) {
        int gr0 = row0 + warp_m*64 + mt*16 + g;
        int gr1 = gr0 + 8;
        #pragma unroll
        for (int nt = 0; nt < 4; nt++) {
            int gc = col0 + warp_n*32 + nt*8 + tg*2;
            float bsv0 = bias[gc], bsv1 = bias[gc+1];
            if (gr0 < M) {
                float c0 = acc[mt][nt][0] + bsv0;
                float c1 = acc[mt][nt][1] + bsv1;
                if (RELU) { c0 = fmaxf(c0, 0.f); c1 = fmaxf(c1, 0.f); }
                C[(size_t)gr0*N + gc]     = c0;
                C[(size_t)gr0*N + gc + 1] = c1;
            }
            if (gr1 < M) {
                float c2 = acc[mt][nt][2] + bsv0;
                float c3 = acc[mt][nt][3] + bsv1;
                if (RELU) { c2 = fmaxf(c2, 0.f); c3 = fmaxf(c3, 0.f); }
                C[(size_t)gr1*N + gc]     = c2;
                C[(size_t)gr1*N + gc + 1] = c3;
            }
        }
    }
}

/* ------------------------- learned-mask projection: qp = q(head) @ w + b ----------------- */
__global__ void lmproj_kernel(const float* __restrict__ q, const float* __restrict__ w,
                              const float* __restrict__ bias, float* __restrict__ out) {
    __shared__ float row[DMODEL];
    int r = blockIdx.x;        /* 8000 */
    int t = threadIdx.x;       /* 128 */
    row[t]       = q[(size_t)r*DMODEL + t];
    row[t+128]   = q[(size_t)r*DMODEL + t + 128];
    row[t+256]   = q[(size_t)r*DMODEL + t + 256];
    row[t+384]   = q[(size_t)r*DMODEL + t + 384];
    __syncthreads();
    int h = t >> 4, p = t & 15;
    float s = bias[p];
    #pragma unroll
    for (int d = 0; d < DK; d++) s += row[h*DK + d]*w[d*PDIM + p];
    out[(size_t)r*(HH*PDIM) + t] = s;
}

/* ------------------------- scores = scale*q.kT + tanh(qp.kpT), per (b,h) ----------------
   64x64 tile, depth 80 (64 qk + 16 mask) in smem. */
__global__ __launch_bounds__(256) void scores_kernel(const float* __restrict__ q,
                                                     const float* __restrict__ k,
                                                     const float* __restrict__ qp,
                                                     const float* __restrict__ kp,
                                                     float* __restrict__ scores) {
    __shared__ float qs[64][81];
    __shared__ float ks[64][81];
    int bh = blockIdx.z;
    int b = bh >> 3, h = bh & 7;
    int l0 = blockIdx.y * 64;
    int s0 = blockIdx.x * 64;
    int tid = threadIdx.x;

    for (int idx = tid; idx < 64*64; idx += 256) {
        int li = idx >> 6, d = idx & 63;
        int l = l0 + li;
        qs[li][d] = (l < LL) ? q[(size_t)(b*LL + l)*DMODEL + h*DK + d] : 0.f;
        int s = s0 + li;
        ks[li][d] = (s < LL) ? k[(size_t)(b*LL + s)*DMODEL + h*DK + d] : 0.f;
    }
    for (int idx = tid; idx < 64*16; idx += 256) {
        int li = idx >> 4, p = idx & 15;
        int l = l0 + li;
        qs[li][64+p] = (l < LL) ? qp[(size_t)(b*LL + l)*(HH*PDIM) + h*PDIM + p] : 0.f;
        int s = s0 + li;
        ks[li][64+p] = (s < LL) ? kp[(size_t)(b*LL + s)*(HH*PDIM) + h*PDIM + p] : 0.f;
    }
    __syncthreads();

    int tx = tid & 15, ty = tid >> 4;
    int li0 = ty*4, si0 = tx*4;
    float acc[4][4], accm[4][4];
    #pragma unroll
    for (int i = 0; i < 4; i++)
        #pragma unroll
        for (int j = 0; j < 4; j++) { acc[i][j] = 0.f; accm[i][j] = 0.f; }

    #pragma unroll 8
    for (int d = 0; d < 64; d++) {
        float a[4], bv[4];
        #pragma unroll
        for (int i = 0; i < 4; i++) a[i]  = qs[li0+i][d];
        #pragma unroll
        for (int j = 0; j < 4; j++) bv[j] = ks[si0+j][d];
        #pragma unroll
        for (int i = 0; i < 4; i++)
            #pragma unroll
            for (int j = 0; j < 4; j++)
                acc[i][j] += a[i]*bv[j];
    }
    #pragma unroll
    for (int d = 64; d < 80; d++) {
        float a[4], bv[4];
        #pragma unroll
        for (int i = 0; i < 4; i++) a[i]  = qs[li0+i][d];
        #pragma unroll
        for (int j = 0; j < 4; j++) bv[j] = ks[si0+j][d];
        #pragma unroll
        for (int i = 0; i < 4; i++)
            #pragma unroll
            for (int j = 0; j < 4; j++)
                accm[i][j] += a[i]*bv[j];
    }

    size_t base = (size_t)bh * LL * LL;
    #pragma unroll
    for (int i = 0; i < 4; i++) {
        int l = l0 + li0 + i;
        if (l >= LL) continue;
        #pragma unroll
        for (int j = 0; j < 4; j++) {
            int s = s0 + si0 + j;
            if (s >= LL) continue;
            scores[base + (size_t)l*LL + s] = acc[i][j]*QKSCALE + tanhf(accm[i][j]);
        }
    }
}

/* ------------------------- row softmax over last dim (1000) ------------------------- */
__global__ void softmax_kernel(float* __restrict__ scores) {
    __shared__ float sbuf[32];
    size_t r = blockIdx.x;              /* 64000 rows */
    float* row = scores + r*LL;
    int t = threadIdx.x;                /* 256 */
    float vals[4];
    float m = -3.4e38f;
    #pragma unroll
    for (int kk = 0; kk < 4; kk++) {
        int i = t + kk*256;
        vals[kk] = (i < LL) ? row[i] : -3.4e38f;
        m = fmaxf(m, vals[kk]);
    }
    m = block_reduce_max(m, sbuf);
    float s = 0.f;
    #pragma unroll
    for (int kk = 0; kk < 4; kk++) {
        int i = t + kk*256;
        if (i < LL) { vals[kk] = expf(vals[kk] - m); s += vals[kk]; }
    }
    s = block_reduce_sum(s, sbuf);
    float inv = 1.f/s;
    #pragma unroll
    for (int kk = 0; kk < 4; kk++) {
        int i = t + kk*256;
        if (i < LL) row[i] = vals[kk]*inv;
    }
}

/* ------------------------- ctx = attn @ v, per (b,h): M=1000,N=64,K=1000 ----------------- */
__global__ __launch_bounds__(256) void ctx_kernel(const float* __restrict__ attn,
                                                  const float* __restrict__ v,
                                                  float* __restrict__ ctx) {
    __shared__ float at[64][33];   /* [l][s] tile, padded */
    __shared__ float vs[32][64];   /* [s][d] tile */
    int bh = blockIdx.z;
    int b = bh >> 3, h = bh & 7;
    int l0 = blockIdx.x * 64;
    int tid = threadIdx.x;
    int tx = tid & 15, ty = tid >> 4;

    float acc[4][4];
    #pragma unroll
    for (int i = 0; i < 4; i++)
        #pragma unroll
        for (int j = 0; j < 4; j++) acc[i][j] = 0.f;

    size_t abase = (size_t)bh * LL * LL;
    for (int s0 = 0; s0 < LL; s0 += 32) {
        for (int idx = tid; idx < 64*32; idx += 256) {
            int li = idx >> 5, si = idx & 31;
            int l = l0 + li, s = s0 + si;
            at[li][si] = (l < LL && s < LL) ? attn[abase + (size_t)l*LL + s] : 0.f;
        }
        for (int idx = tid; idx < 32*64; idx += 256) {
            int si = idx >> 6, d = idx & 63;
            int s = s0 + si;
            vs[si][d] = (s < LL) ? v[(size_t)(b*LL + s)*DMODEL + h*DK + d] : 0.f;
        }
        __syncthreads();
        #pragma unroll 8
        for (int s = 0; s < 32; s++) {
            float a[4], bv[4];
            #pragma unroll
            for (int i = 0; i < 4; i++) a[i] = at[ty*4+i][s];
            *(float4*)bv = *(float4*)&vs[s][tx*4];
            #pragma unroll
            for (int i = 0; i < 4; i++)
                #pragma unroll
                for (int j = 0; j < 4; j++)
                    acc[i][j] += a[i]*bv[j];
        }
        __syncthreads();
    }

    #pragma unroll
    for (int i = 0; i < 4; i++) {
        int l = l0 + ty*4 + i;
        if (l >= LL) continue;
        #pragma unroll
        for (int j = 0; j < 4; j++) {
            int d = tx*4 + j;
            ctx[(size_t)(b*LL + l)*DMODEL + h*DK + d] = acc[i][j];
        }
    }
}

/* ------------------------- h = LN(h + res) ------------------------- */
__global__ void ln_residual_kernel(float* __restrict__ h, const float* __restrict__ res,
                                   const float* __restrict__ g, const float* __restrict__ b) {
    __shared__ float sbuf[32];
    int r = blockIdx.x, t = threadIdx.x;   /* 256 */
    size_t base = (size_t)r*DMODEL;
    float v0 = h[base + t]       + res[base + t];
    float v1 = h[base + t + 256] + res[base + t + 256];
    float mean = block_reduce_sum(v0 + v1, sbuf) * (1.f/DMODEL);
    float d0 = v0 - mean, d1 = v1 - mean;
    float var = block_reduce_sum(d0*d0 + d1*d1, sbuf) * (1.f/DMODEL);
    float inv = rsqrtf(var + LEPS);
    h[base + t]       = d0*inv*g[t]     + b[t];
    h[base + t + 256] = d1*inv*g[t+256] + b[t+256];
}

/* ------------------------- h = LN(LN(h+y)+y)  (the double-norm2 quirk) ------------------- */
__global__ void double_ln_kernel(float* __restrict__ h, const float* __restrict__ y,
                                 const float* __restrict__ g, const float* __restrict__ b) {
    __shared__ float sbuf[32];
    int r = blockIdx.x, t = threadIdx.x;   /* 256 */
    size_t base = (size_t)r*DMODEL;
    float y0 = y[base + t], y1 = y[base + t + 256];
    float t0 = h[base + t] + y0, t1 = h[base + t + 256] + y1;
    float mean = block_reduce_sum(t0 + t1, sbuf) * (1.f/DMODEL);
    float d0 = t0 - mean, d1 = t1 - mean;
    float var = block_reduce_sum(d0*d0 + d1*d1, sbuf) * (1.f/DMODEL);
    float inv = rsqrtf(var + LEPS);
    float h20 = d0*inv*g[t]     + b[t];
    float h21 = d1*inv*g[t+256] + b[t+256];
    /* second LN of (h2 + y) */
    float u0 = h20 + y0, u1 = h21 + y1;
    mean = block_reduce_sum(u0 + u1, sbuf) * (1.f/DMODEL);
    d0 = u0 - mean; d1 = u1 - mean;
    var = block_reduce_sum(d0*d0 + d1*d1, sbuf) * (1.f/DMODEL);
    inv = rsqrtf(var + LEPS);
    h[base + t]       = d0*inv*g[t]     + b[t];
    h[base + t + 256] = d1*inv*g[t+256] + b[t+256];
}

/* ------------------------- final: LN(last token) @ fc_w + fc_b ------------------------- */
__global__ void final_kernel(const float* __restrict__ h, const float* __restrict__ gn,
                             const float* __restrict__ bn, const float* __restrict__ fw,
                             const float* __restrict__ fb, float* __restrict__ out) {
    __shared__ float sbuf[32];
    __shared__ float row[DMODEL];
    int b = blockIdx.x, t = threadIdx.x;   /* 256 */
    const float* hr = h + (size_t)(b*LL + (LL-1))*DMODEL;
    float v0 = hr[t], v1 = hr[t + 256];
    float mean = block_reduce_sum(v0 + v1, sbuf) * (1.f/DMODEL);
    float d0 = v0 - mean, d1 = v1 - mean;
    float var = block_reduce_sum(d0*d0 + d1*d1, sbuf) * (1.f/DMODEL);
    float inv = rsqrtf(var + LEPS);
    row[t]       = d0*inv*gn[t]     + bn[t];
    row[t + 256] = d1*inv*gn[t+256] + bn[t+256];
    __syncthreads();
    for (int p = t; p < NPRED; p += 256) {
        float s = fb[p];
        for (int d = 0; d < DMODEL; d++) s += row[d]*fw[(size_t)d*NPRED + p];
        out[(size_t)b*NPRED + p] = s;
    }
}

/* ------------------------- launch ------------------------- */
extern "C" void kernel_launch(void* const* d_in, const int* in_sizes, int n_in,
                              void* d_out, int out_size) {
    const float* x     = (const float*)d_in[0];
    const float* emb_w = (const float*)d_in[1];
    const float* emb_b = (const float*)d_in[2];
    const float* pe    = (const float*)d_in[3];
    const float* Wq    = (const float*)d_in[4];
    const float* bq    = (const float*)d_in[5];
    const float* Wk    = (const float*)d_in[6];
    const float* bk    = (const float*)d_in[7];
    const float* Wv    = (const float*)d_in[8];
    const float* bv    = (const float*)d_in[9];
    const float* Wo    = (const float*)d_in[10];
    const float* bo    = (const float*)d_in[11];
    const float* W1    = (const float*)d_in[12];
    const float* b1    = (const float*)d_in[13];
    const float* W2    = (const float*)d_in[14];
    const float* b2    = (const float*)d_in[15];
    const float* g1    = (const float*)d_in[16];
    const float* be1   = (const float*)d_in[17];
    const float* g2    = (const float*)d_in[18];
    const float* be2   = (const float*)d_in[19];
    const float* lm_qw = (const float*)d_in[20];
    const float* lm_qb = (const float*)d_in[21];
    const float* lm_kw = (const float*)d_in[22];
    const float* lm_kb = (const float*)d_in[23];
    const float* gn    = (const float*)d_in[24];
    const float* bn    = (const float*)d_in[25];
    const float* fc_w  = (const float*)d_in[26];
    const float* fc_b  = (const float*)d_in[27];
    float* out = (float*)d_out;

    float *h, *q, *k, *v, *ctx, *y, *qp, *kp, *ffn, *scores;
    cudaGetSymbolAddress((void**)&h,      g_h);
    cudaGetSymbolAddress((void**)&q,      g_q);
    cudaGetSymbolAddress((void**)&k,      g_k);
    cudaGetSymbolAddress((void**)&v,      g_v);
    cudaGetSymbolAddress((void**)&ctx,    g_ctx);
    cudaGetSymbolAddress((void**)&y,      g_y);
    cudaGetSymbolAddress((void**)&qp,     g_qp);
    cudaGetSymbolAddress((void**)&kp,     g_kp);
    cudaGetSymbolAddress((void**)&ffn,    g_ffn);
    cudaGetSymbolAddress((void**)&scores, g_scores);

    embed_kernel<<<ROWS, 256>>>(x, emb_w, emb_b, pe, h);

    dim3 g512(DMODEL/128, (ROWS + 127)/128);
    dim3 gff (DFF/128,    (ROWS + 127)/128);
    dim3 gsc (16, 16, BB*HH);
    dim3 gcx (16, 1, BB*HH);

    for (int i = 0; i < NLAYERS; i++) {
        const float* Wq_i = Wq + (size_t)i*DMODEL*DMODEL;
        const float* Wk_i = Wk + (size_t)i*DMODEL*DMODEL;
        const float* Wv_i = Wv + (size_t)i*DMODEL*DMODEL;
        const float* Wo_i = Wo + (size_t)i*DMODEL*DMODEL;
        const float* bq_i = bq + (size_t)i*DMODEL;
        const float* bk_i = bk + (size_t)i*DMODEL;
        const float* bv_i = bv + (size_t)i*DMODEL;
        const float* bo_i = bo + (size_t)i*DMODEL;
        const float* W1_i = W1 + (size_t)i*DMODEL*DFF;
        const float* b1_i = b1 + (size_t)i*DFF;
        const float* W2_i = W2 + (size_t)i*DFF*DMODEL;
        const float* b2_i = b2 + (size_t)i*DMODEL;
        const float* g1_i = g1 + (size_t)i*DMODEL;
        const float* be1_i= be1+ (size_t)i*DMODEL;
        const float* g2_i = g2 + (size_t)i*DMODEL;
        const float* be2_i= be2+ (size_t)i*DMODEL;

        gemm_tf32<0><<<g512, 256>>>(h, Wq_i, bq_i, q, ROWS, DMODEL, DMODEL);
        gemm_tf32<0><<<g512, 256>>>(h, Wk_i, bk_i, k, ROWS, DMODEL, DMODEL);
        gemm_tf32<0><<<g512, 256>>>(h, Wv_i, bv_i, v, ROWS, DMODEL, DMODEL);

        lmproj_kernel<<<ROWS, 128>>>(q, lm_qw, lm_qb, qp);
        lmproj_kernel<<<ROWS, 128>>>(k, lm_kw, lm_kb, kp);

        scores_kernel<<<gsc, 256>>>(q, k, qp, kp, scores);
        softmax_kernel<<<BB*HH*LL, 256>>>(scores);
        ctx_kernel<<<gcx, 256>>>(scores, v, ctx);

        /* o-projection reuses q buffer */
        gemm_tf32<0><<<g512, 256>>>(ctx, Wo_i, bo_i, q, ROWS, DMODEL, DMODEL);
        ln_residual_kernel<<<ROWS, 256>>>(h, q, g1_i, be1_i);

        gemm_tf32<1><<<gff, 256>>>(h, W1_i, b1_i, ffn, ROWS, DFF, DMODEL);
        gemm_tf32<0><<<g512, 256>>>(ffn, W2_i, b2_i, y, ROWS, DMODEL, DFF);
        double_ln_kernel<<<ROWS, 256>>>(h, y, g2_i, be2_i);
    }

    final_kernel<<<BB, 256>>>(h, gn, bn, fc_w, fc_b, out);
    (void)in_sizes; (void)n_in; (void)out_size;
}